// round 2
// baseline (speedup 1.0000x reference)
#include <cuda_runtime.h>

#define IN_F   64
#define OUT_F  100
#define MAX_NODES 100000

// Scratch (allocation-free rule: device globals)
__device__ float g_S[(size_t)MAX_NODES * IN_F];   // segment sums [n_nodes, 64]
__device__ float g_deg[MAX_NODES];                // in-degree per node

// ---------------------------------------------------------------------------
// Kernel 1: zero scratch — float4 grid-stride
// ---------------------------------------------------------------------------
__global__ void zero_kernel(int nS4, int nD4) {
    int stride = gridDim.x * blockDim.x;
    int t = blockIdx.x * blockDim.x + threadIdx.x;
    float4 z = make_float4(0.f, 0.f, 0.f, 0.f);
    float4* S4 = reinterpret_cast<float4*>(g_S);
    float4* D4 = reinterpret_cast<float4*>(g_deg);
    for (int i = t; i < nS4; i += stride) S4[i] = z;
    for (int i = t; i < nD4; i += stride) D4[i] = z;
}

// ---------------------------------------------------------------------------
// Kernel 2: scatter-accumulate edges into S with vector float4 RED atomics.
// Grid-stride, 4 chunks per iteration for MLP=4 on the e-loads.
// ---------------------------------------------------------------------------
__device__ __forceinline__ void red_chunk(int i, const float4* __restrict__ e4,
                                          const int* __restrict__ dst,
                                          const float4& v) {
    int edge = i >> 4;
    int c    = i & 15;
    int d    = __ldg(dst + edge);
    float* p = g_S + (size_t)d * IN_F + c * 4;
    asm volatile("red.global.add.v4.f32 [%0], {%1, %2, %3, %4};"
                 :: "l"(p), "f"(v.x), "f"(v.y), "f"(v.z), "f"(v.w)
                 : "memory");
    if (c == 0) atomicAdd(g_deg + d, 1.0f);
}

__global__ __launch_bounds__(256)
void scatter_kernel(const float4* __restrict__ e4,
                    const int* __restrict__ dst,
                    int n_edges) {
    int total  = n_edges * 16;          // float4 chunks
    int stride = gridDim.x * blockDim.x;
    int t0 = blockIdx.x * blockDim.x + threadIdx.x;

    int i = t0;
    // main loop: 4 batched chunks (independent loads issue back-to-back)
    for (; i + 3 * stride < total; i += 4 * stride) {
        int i0 = i, i1 = i + stride, i2 = i + 2 * stride, i3 = i + 3 * stride;
        float4 v0 = e4[i0];
        float4 v1 = e4[i1];
        float4 v2 = e4[i2];
        float4 v3 = e4[i3];
        red_chunk(i0, e4, dst, v0);
        red_chunk(i1, e4, dst, v1);
        red_chunk(i2, e4, dst, v2);
        red_chunk(i3, e4, dst, v3);
    }
    for (; i < total; i += stride) {
        float4 v = e4[i];
        red_chunk(i, e4, dst, v);
    }
}

// ---------------------------------------------------------------------------
// Kernel 3: h[n,o] = (S[n,:] . W[o,:]) / max(deg,1) + b[o] * (deg>0)
// Tile: 64 nodes x 100 outs per block; 160 threads; per-thread 8 nodes x 5 outs.
// ---------------------------------------------------------------------------
#define NT   64      // nodes per block
#define NG   8       // node groups (8 nodes each)
#define OG   20      // out groups (5 outs each)
#define TPB  (NG * OG)   // 160 threads
#define SS   65      // padded Ssm row stride

__global__ __launch_bounds__(TPB)
void gemm_kernel(const float* __restrict__ W,
                 const float* __restrict__ b,
                 float* __restrict__ out,
                 int n_nodes) {
    __shared__ float Ssm[NT * SS];          // 16.6 KB
    __shared__ float Wsm[IN_F * OUT_F];     // 25.6 KB, [k][o]
    __shared__ float bsm[OUT_F];
    __shared__ float invd[NT];
    __shared__ float bfac[NT];

    int tid   = threadIdx.x;
    int node0 = blockIdx.x * NT;

    // W transpose load: Wsm[k*100 + o] = W[o*64 + k]  (coalesced global read)
    for (int i = tid; i < IN_F * OUT_F; i += TPB) {
        int o = i / IN_F, k = i % IN_F;
        Wsm[k * OUT_F + o] = W[i];
    }
    for (int i = tid; i < OUT_F; i += TPB) bsm[i] = b[i];

    // S tile load (float4 global, scalar STS into padded rows)
    for (int i = tid; i < NT * 16; i += TPB) {
        int r = i >> 4, c = i & 15;
        int node = node0 + r;
        float4 v = make_float4(0.f, 0.f, 0.f, 0.f);
        if (node < n_nodes)
            v = reinterpret_cast<const float4*>(g_S)[(size_t)node * 16 + c];
        float* p = &Ssm[r * SS + c * 4];
        p[0] = v.x; p[1] = v.y; p[2] = v.z; p[3] = v.w;
    }

    // degree -> inverse + bias mask
    for (int i = tid; i < NT; i += TPB) {
        int node = node0 + i;
        float dg = (node < n_nodes) ? g_deg[node] : 0.0f;
        invd[i] = (dg > 0.0f) ? (1.0f / dg) : 0.0f;
        bfac[i] = (dg > 0.0f) ? 1.0f : 0.0f;
    }
    __syncthreads();

    int og = tid % OG;   // 0..19 -> outs [og*5, og*5+5)
    int ng = tid / OG;   // 0..7  -> nodes [ng*8, ng*8+8)

    float acc[8][5];
#pragma unroll
    for (int j = 0; j < 8; j++)
#pragma unroll
        for (int i = 0; i < 5; i++) acc[j][i] = 0.0f;

    const float* wp = &Wsm[og * 5];
    const float* sp = &Ssm[ng * 8 * SS];

#pragma unroll 4
    for (int k = 0; k < IN_F; k++) {
        float w0 = wp[k * OUT_F + 0];
        float w1 = wp[k * OUT_F + 1];
        float w2 = wp[k * OUT_F + 2];
        float w3 = wp[k * OUT_F + 3];
        float w4 = wp[k * OUT_F + 4];
#pragma unroll
        for (int j = 0; j < 8; j++) {
            float s = sp[j * SS + k];
            acc[j][0] += s * w0;
            acc[j][1] += s * w1;
            acc[j][2] += s * w2;
            acc[j][3] += s * w3;
            acc[j][4] += s * w4;
        }
    }

    // writeback: scale by 1/deg, add masked bias
#pragma unroll
    for (int j = 0; j < 8; j++) {
        int lr   = ng * 8 + j;
        int node = node0 + lr;
        if (node >= n_nodes) continue;
        float inv = invd[lr];
        float bf  = bfac[lr];
        float* op = out + (size_t)node * OUT_F + og * 5;
#pragma unroll
        for (int i = 0; i < 5; i++)
            op[i] = acc[j][i] * inv + bsm[og * 5 + i] * bf;
    }
}

// ---------------------------------------------------------------------------
extern "C" void kernel_launch(void* const* d_in, const int* in_sizes, int n_in,
                              void* d_out, int out_size) {
    const float* e   = (const float*)d_in[0];
    const int*   dst = (const int*)d_in[1];
    const float* W   = (const float*)d_in[2];
    const float* b   = (const float*)d_in[3];
    float*       out = (float*)d_out;

    int n_edges = in_sizes[1];              // dst element count
    int n_nodes = out_size / OUT_F;         // 100000

    int nS4 = (n_nodes * IN_F) / 4;
    int nD4 = (n_nodes + 3) / 4;
    zero_kernel<<<592, 256>>>(nS4, nD4);    // 592 = 148 SM * 4

    scatter_kernel<<<2048, 256>>>((const float4*)e, dst, n_edges);

    gemm_kernel<<<(n_nodes + NT - 1) / NT, TPB>>>(W, b, out, n_nodes);
}

// round 5
// speedup vs baseline: 1.2011x; 1.2011x over previous
#include <cuda_runtime.h>

#define IN_F   64
#define OUT_F  100
#define MAX_NODES 100000
#define MAX_EDGES 1600000
#define SCAN_TILE 1024
#define NB_SCAN ((MAX_NODES + SCAN_TILE - 1) / SCAN_TILE)   // 98

// Scratch (allocation-free rule: device globals)
__device__ int   g_cnt[MAX_NODES];            // per-node edge count
__device__ int   g_off[MAX_NODES + 1];        // CSR offsets
__device__ int   g_cur[MAX_NODES];            // fill cursors
__device__ int   g_bsum[NB_SCAN];             // scan partials
__device__ int   g_bpre[NB_SCAN];             // scan block prefixes
__device__ int   g_eidx[MAX_EDGES];           // edge ids sorted by dst
__device__ float g_S[(size_t)MAX_NODES * IN_F];  // segment sums

// ---------------------------------------------------------------------------
// 1. zero counts
// ---------------------------------------------------------------------------
__global__ void zero_cnt_kernel(int n_nodes) {
    int i = blockIdx.x * blockDim.x + threadIdx.x;
    if (i < n_nodes) g_cnt[i] = 0;
}

// ---------------------------------------------------------------------------
// 2. histogram of dst
// ---------------------------------------------------------------------------
__global__ void hist_kernel(const int* __restrict__ dst, int n_edges) {
    int i = blockIdx.x * blockDim.x + threadIdx.x;
    if (i < n_edges) atomicAdd(&g_cnt[__ldg(dst + i)], 1);
}

// ---------------------------------------------------------------------------
// 3a. scan pass 1: per-block (1024 elems) totals
// ---------------------------------------------------------------------------
__global__ void scan1_kernel(int n) {
    __shared__ int sm[256];
    int tid  = threadIdx.x;
    int base = blockIdx.x * SCAN_TILE + tid * 4;
    int s = 0;
#pragma unroll
    for (int k = 0; k < 4; k++)
        if (base + k < n) s += g_cnt[base + k];
    sm[tid] = s;
    __syncthreads();
    for (int d = 128; d > 0; d >>= 1) {
        if (tid < d) sm[tid] += sm[tid + d];
        __syncthreads();
    }
    if (tid == 0) g_bsum[blockIdx.x] = sm[0];
}

// ---------------------------------------------------------------------------
// 3b. scan pass 2: serial exclusive scan over block totals (<=98 values)
// ---------------------------------------------------------------------------
__global__ void scan2_kernel(int nb, int n_nodes) {
    if (threadIdx.x == 0) {
        int run = 0;
        for (int b = 0; b < nb; b++) {
            g_bpre[b] = run;
            run += g_bsum[b];
        }
        g_off[n_nodes] = run;
    }
}

// ---------------------------------------------------------------------------
// 3c. scan pass 3: write per-element exclusive offsets + cursors
// ---------------------------------------------------------------------------
__global__ void scan3_kernel(int n) {
    __shared__ int sm[256];
    int tid  = threadIdx.x;
    int base = blockIdx.x * SCAN_TILE + tid * 4;
    int l[4];
    int s = 0;
#pragma unroll
    for (int k = 0; k < 4; k++) {
        l[k] = (base + k < n) ? g_cnt[base + k] : 0;
        s += l[k];
    }
    sm[tid] = s;
    __syncthreads();
    // Hillis-Steele inclusive scan over per-thread sums
    for (int d = 1; d < 256; d <<= 1) {
        int v = (tid >= d) ? sm[tid - d] : 0;
        __syncthreads();
        sm[tid] += v;
        __syncthreads();
    }
    int run = g_bpre[blockIdx.x] + sm[tid] - s;   // exclusive prefix
#pragma unroll
    for (int k = 0; k < 4; k++) {
        if (base + k < n) {
            g_off[base + k] = run;
            g_cur[base + k] = run;
            run += l[k];
        }
    }
}

// ---------------------------------------------------------------------------
// 4. fill edge index (counting-sort scatter of edge ids)
// ---------------------------------------------------------------------------
__global__ void fill_kernel(const int* __restrict__ dst, int n_edges) {
    int i = blockIdx.x * blockDim.x + threadIdx.x;
    if (i < n_edges) {
        int d = __ldg(dst + i);
        int p = atomicAdd(&g_cur[d], 1);
        g_eidx[p] = i;
    }
}

// ---------------------------------------------------------------------------
// 5. gather: one warp per node; sum edge feature rows (256B each) in regs.
//    Writes EVERY row of g_S (zeros for deg-0 nodes) -> no S zeroing pass.
//    4-edge batches: all index loads, then all feature loads (MLP >= 4).
// ---------------------------------------------------------------------------
__global__ __launch_bounds__(256)
void gather_kernel(const float2* __restrict__ e2, int n_nodes) {
    int w    = (blockIdx.x * blockDim.x + threadIdx.x) >> 5;
    int lane = threadIdx.x & 31;
    if (w >= n_nodes) return;
    int s = g_off[w], t = g_off[w + 1];

    float sx = 0.f, sy = 0.f;
    int j = s;
    for (; j + 4 <= t; j += 4) {
        int e0 = __ldg(g_eidx + j);
        int e1 = __ldg(g_eidx + j + 1);
        int ee2 = __ldg(g_eidx + j + 2);
        int e3 = __ldg(g_eidx + j + 3);
        float2 v0 = e2[(size_t)e0 * 32 + lane];
        float2 v1 = e2[(size_t)e1 * 32 + lane];
        float2 v2 = e2[(size_t)ee2 * 32 + lane];
        float2 v3 = e2[(size_t)e3 * 32 + lane];
        sx += (v0.x + v1.x) + (v2.x + v3.x);
        sy += (v0.y + v1.y) + (v2.y + v3.y);
    }
    for (; j < t; j++) {
        int eid = __ldg(g_eidx + j);
        float2 v = e2[(size_t)eid * 32 + lane];
        sx += v.x;
        sy += v.y;
    }
    reinterpret_cast<float2*>(g_S)[(size_t)w * 32 + lane] = make_float2(sx, sy);
}

// ---------------------------------------------------------------------------
// 6. GEMM: h[n,o] = (S[n,:] . W[o,:]) / max(deg,1) + b[o] * (deg>0)
// ---------------------------------------------------------------------------
#define NT   64
#define NG   8
#define OG   20
#define TPB  (NG * OG)   // 160
#define SS   65

__global__ __launch_bounds__(TPB)
void gemm_kernel(const float* __restrict__ W,
                 const float* __restrict__ b,
                 float* __restrict__ out,
                 int n_nodes) {
    __shared__ float Ssm[NT * SS];
    __shared__ float Wsm[IN_F * OUT_F];
    __shared__ float bsm[OUT_F];
    __shared__ float invd[NT];
    __shared__ float bfac[NT];

    int tid   = threadIdx.x;
    int node0 = blockIdx.x * NT;

    for (int i = tid; i < IN_F * OUT_F; i += TPB) {
        int o = i / IN_F, k = i % IN_F;
        Wsm[k * OUT_F + o] = W[i];
    }
    for (int i = tid; i < OUT_F; i += TPB) bsm[i] = b[i];

    for (int i = tid; i < NT * 16; i += TPB) {
        int r = i >> 4, c = i & 15;
        int node = node0 + r;
        float4 v = make_float4(0.f, 0.f, 0.f, 0.f);
        if (node < n_nodes)
            v = reinterpret_cast<const float4*>(g_S)[(size_t)node * 16 + c];
        float* p = &Ssm[r * SS + c * 4];
        p[0] = v.x; p[1] = v.y; p[2] = v.z; p[3] = v.w;
    }

    for (int i = tid; i < NT; i += TPB) {
        int node = node0 + i;
        int dg = 0;
        if (node < n_nodes) dg = g_off[node + 1] - g_off[node];
        invd[i] = (dg > 0) ? (1.0f / (float)dg) : 0.0f;
        bfac[i] = (dg > 0) ? 1.0f : 0.0f;
    }
    __syncthreads();

    int og = tid % OG;
    int ng = tid / OG;

    float acc[8][5];
#pragma unroll
    for (int j = 0; j < 8; j++)
#pragma unroll
        for (int i = 0; i < 5; i++) acc[j][i] = 0.0f;

    const float* wp = &Wsm[og * 5];
    const float* sp = &Ssm[ng * 8 * SS];

#pragma unroll 4
    for (int k = 0; k < IN_F; k++) {
        float w0 = wp[k * OUT_F + 0];
        float w1 = wp[k * OUT_F + 1];
        float w2 = wp[k * OUT_F + 2];
        float w3 = wp[k * OUT_F + 3];
        float w4 = wp[k * OUT_F + 4];
#pragma unroll
        for (int j = 0; j < 8; j++) {
            float s = sp[j * SS + k];
            acc[j][0] += s * w0;
            acc[j][1] += s * w1;
            acc[j][2] += s * w2;
            acc[j][3] += s * w3;
            acc[j][4] += s * w4;
        }
    }

#pragma unroll
    for (int j = 0; j < 8; j++) {
        int lr   = ng * 8 + j;
        int node = node0 + lr;
        if (node >= n_nodes) continue;
        float inv = invd[lr];
        float bf  = bfac[lr];
        float* op = out + (size_t)node * OUT_F + og * 5;
#pragma unroll
        for (int i = 0; i < 5; i++)
            op[i] = acc[j][i] * inv + bsm[og * 5 + i] * bf;
    }
}

// ---------------------------------------------------------------------------
extern "C" void kernel_launch(void* const* d_in, const int* in_sizes, int n_in,
                              void* d_out, int out_size) {
    const float* e   = (const float*)d_in[0];
    const int*   dst = (const int*)d_in[1];
    const float* W   = (const float*)d_in[2];
    const float* b   = (const float*)d_in[3];
    float*       out = (float*)d_out;

    int n_edges = in_sizes[1];
    int n_nodes = out_size / OUT_F;
    int nb      = (n_nodes + SCAN_TILE - 1) / SCAN_TILE;

    zero_cnt_kernel<<<(n_nodes + 255) / 256, 256>>>(n_nodes);
    hist_kernel<<<(n_edges + 255) / 256, 256>>>(dst, n_edges);
    scan1_kernel<<<nb, 256>>>(n_nodes);
    scan2_kernel<<<1, 32>>>(nb, n_nodes);
    scan3_kernel<<<nb, 256>>>(n_nodes);
    fill_kernel<<<(n_edges + 255) / 256, 256>>>(dst, n_edges);

    int gwarps = n_nodes;                       // one warp per node
    gather_kernel<<<(gwarps * 32 + 255) / 256, 256>>>((const float2*)e, n_nodes);

    gemm_kernel<<<(n_nodes + NT - 1) / NT, TPB>>>(W, b, out, n_nodes);
}